// round 8
// baseline (speedup 1.0000x reference)
#include <cuda_runtime.h>

#define BB   32
#define NNQ  512
#define DD   512
#define HH   8
#define DKK  64
#define LL   3
#define FFF  2048
#define BNR  (BB*NNQ)   /* 16384 rows */
#define EPSV 1e-5f

// ---------------- static scratch (no allocations allowed) ----------------
__device__ float g_h  [BNR*DD];          // 32 MB
__device__ float g_y  [BNR*DD];          // 32 MB
__device__ float g_att[BNR*DD];          // 32 MB
__device__ float g_qkv[3*BNR*DD];        // 96 MB
__device__ float g_ff [BNR*FFF];         // 128 MB
__device__ float g_wp [LL*3*DD*DD];      // packed Wq/Wk/Wv, 9 MB
__device__ float g_sum[DD];
__device__ float g_sq [DD];

// ---------------- weight packing: Wq/Wk/Wv [L,H,D,DK] -> [L,t][D][H*DK] ----
__global__ void pack_k(const float* __restrict__ Wq, const float* __restrict__ Wk,
                       const float* __restrict__ Wv, float* __restrict__ wp)
{
    int idx = blockIdx.x * blockDim.x + threadIdx.x;
    const int PER = DD * DD;                  // 262144 per (l,t)
    if (idx >= LL * 3 * PER) return;
    int lt  = idx / PER;
    int pos = idx - lt * PER;
    int l = lt / 3, t = lt - l * 3;
    int d  = pos >> 9;
    int hk = pos & 511;
    int h  = hk >> 6;
    int k  = hk & 63;
    const float* src = (t == 0) ? Wq : (t == 1) ? Wk : Wv;
    wp[idx] = src[((size_t)(l * HH + h) * DD + d) * DKK + k];
}

// ---------------- embed: h = x @ We^T + be  (NODE_DIM = 2) ----------------
__global__ void embed_k(const float* __restrict__ x, const float* __restrict__ We,
                        const float* __restrict__ be, float* __restrict__ h)
{
    int idx = blockIdx.x * blockDim.x + threadIdx.x;
    if (idx >= BNR * DD) return;
    int bn = idx >> 9;
    int d  = idx & 511;
    h[idx] = x[bn * 2] * We[d * 2] + x[bn * 2 + 1] * We[d * 2 + 1] + be[d];
}

// ---------------- generic tiled FP32 GEMM: C = op(A*B (+bias) (+res)) -----
// A: [M,K] row-major.  BT=false: B is [K,N] row-major.  BT=true: B is [N,K].
template<bool BT, bool BIAS, bool RELU, bool RES>
__global__ void __launch_bounds__(256)
gemm_k(const float* __restrict__ A, const float* __restrict__ B,
       const float* __restrict__ bias, const float* __restrict__ res,
       float* __restrict__ C, int M, int N, int K)
{
    __shared__ float As[16][128];
    __shared__ float Bs[16][128];
    int tid = threadIdx.x;
    int tx = tid & 15, ty = tid >> 4;
    int m0 = blockIdx.y * 128, n0 = blockIdx.x * 128;

    float acc[8][8];
#pragma unroll
    for (int i = 0; i < 8; i++)
#pragma unroll
        for (int j = 0; j < 8; j++) acc[i][j] = 0.f;

    int arow = tid >> 1;           // 0..127
    int akh  = (tid & 1) * 8;      // 0 or 8
    const float* Aptr = A + (size_t)(m0 + arow) * K + akh;

    for (int k0 = 0; k0 < K; k0 += 16) {
        // A tile -> As[k][m] (transposed store)
        {
            float4 a0 = *(const float4*)(Aptr + k0);
            float4 a1 = *(const float4*)(Aptr + k0 + 4);
            As[akh + 0][arow] = a0.x; As[akh + 1][arow] = a0.y;
            As[akh + 2][arow] = a0.z; As[akh + 3][arow] = a0.w;
            As[akh + 4][arow] = a1.x; As[akh + 5][arow] = a1.y;
            As[akh + 6][arow] = a1.z; As[akh + 7][arow] = a1.w;
        }
        if (BT) {
            const float* Bp = B + (size_t)(n0 + arow) * K + k0 + akh;
            float4 b0 = *(const float4*)Bp;
            float4 b1 = *(const float4*)(Bp + 4);
            Bs[akh + 0][arow] = b0.x; Bs[akh + 1][arow] = b0.y;
            Bs[akh + 2][arow] = b0.z; Bs[akh + 3][arow] = b0.w;
            Bs[akh + 4][arow] = b1.x; Bs[akh + 5][arow] = b1.y;
            Bs[akh + 6][arow] = b1.z; Bs[akh + 7][arow] = b1.w;
        } else {
            int kr = tid >> 4;             // 0..15
            int cb = (tid & 15) * 8;       // 0..120
            const float* Bp = B + (size_t)(k0 + kr) * N + n0 + cb;
            float4 b0 = *(const float4*)Bp;
            float4 b1 = *(const float4*)(Bp + 4);
            *(float4*)&Bs[kr][cb]     = b0;
            *(float4*)&Bs[kr][cb + 4] = b1;
        }
        __syncthreads();
#pragma unroll
        for (int kk = 0; kk < 16; kk++) {
            float4 ra0 = *(const float4*)&As[kk][ty * 8];
            float4 ra1 = *(const float4*)&As[kk][ty * 8 + 4];
            float4 rb0 = *(const float4*)&Bs[kk][tx * 8];
            float4 rb1 = *(const float4*)&Bs[kk][tx * 8 + 4];
            float ra[8] = {ra0.x, ra0.y, ra0.z, ra0.w, ra1.x, ra1.y, ra1.z, ra1.w};
            float rb[8] = {rb0.x, rb0.y, rb0.z, rb0.w, rb1.x, rb1.y, rb1.z, rb1.w};
#pragma unroll
            for (int i = 0; i < 8; i++)
#pragma unroll
                for (int j = 0; j < 8; j++) acc[i][j] += ra[i] * rb[j];
        }
        __syncthreads();
    }

    int row0 = m0 + ty * 8, col0 = n0 + tx * 8;
    float bj[8];
    if (BIAS) {
        float4 b0 = *(const float4*)&bias[col0];
        float4 b1 = *(const float4*)&bias[col0 + 4];
        bj[0]=b0.x; bj[1]=b0.y; bj[2]=b0.z; bj[3]=b0.w;
        bj[4]=b1.x; bj[5]=b1.y; bj[6]=b1.z; bj[7]=b1.w;
    }
#pragma unroll
    for (int i = 0; i < 8; i++) {
        int r = row0 + i;
        float v[8];
#pragma unroll
        for (int j = 0; j < 8; j++) v[j] = acc[i][j];
        if (BIAS) {
#pragma unroll
            for (int j = 0; j < 8; j++) v[j] += bj[j];
        }
        if (RES) {
            float4 r0 = *(const float4*)&res[(size_t)r * N + col0];
            float4 r1 = *(const float4*)&res[(size_t)r * N + col0 + 4];
            v[0]+=r0.x; v[1]+=r0.y; v[2]+=r0.z; v[3]+=r0.w;
            v[4]+=r1.x; v[5]+=r1.y; v[6]+=r1.z; v[7]+=r1.w;
        }
        if (RELU) {
#pragma unroll
            for (int j = 0; j < 8; j++) v[j] = fmaxf(v[j], 0.f);
        }
        *(float4*)&C[(size_t)r * N + col0]     = make_float4(v[0], v[1], v[2], v[3]);
        *(float4*)&C[(size_t)r * N + col0 + 4] = make_float4(v[4], v[5], v[6], v[7]);
    }
}

// ---------------- attention: per (b,h), 32-query tiles, scores in SMEM ----
// Q/K/V layout: row (b*N+n), col h*64+k (row stride 512)
__global__ void __launch_bounds__(256)
attn_k(const float* __restrict__ Qg, const float* __restrict__ Kg,
       const float* __restrict__ Vg, float* __restrict__ O)
{
    extern __shared__ float sm[];
    float* Qs = sm;               // [32][64]   2048 floats
    float* Ks = sm + 2048;        // [64][65]   4160 floats (also V tile)
    float* Ss = sm + 6208;        // [32][520]  16640 floats
    int tid = threadIdx.x;
    int bh = blockIdx.y;
    int b = bh >> 3, h = bh & 7;
    size_t base = (size_t)b * NNQ * DD + h * DKK;
    const float* Qp = Qg + base;
    const float* Kp = Kg + base;
    const float* Vp = Vg + base;
    int q0 = blockIdx.x * 32;

    // load Q tile, pre-scaled by 1/sqrt(64) = 0.125
    {
        int f = tid;
#pragma unroll
        for (int it = 0; it < 2; it++, f += 256) {
            int row = f >> 4, c4 = (f & 15) * 4;
            float4 v = *(const float4*)(Qp + (size_t)(q0 + row) * DD + c4);
            float* dst = &Qs[row * 64 + c4];
            dst[0] = v.x * 0.125f; dst[1] = v.y * 0.125f;
            dst[2] = v.z * 0.125f; dst[3] = v.w * 0.125f;
        }
    }

    int qi = tid >> 3;   // 0..31 (query within tile)
    int l8 = tid & 7;    // 8-lane group within a query row

    // ---- scores S = (Q*scale) K^T ----
    for (int kt = 0; kt < 8; kt++) {
        __syncthreads();  // prev compute done (and Q loaded on first iter)
        int f = tid;
#pragma unroll
        for (int it = 0; it < 4; it++, f += 256) {
            int row = f >> 4, c4 = (f & 15) * 4;
            float4 v = *(const float4*)(Kp + (size_t)(kt * 64 + row) * DD + c4);
            float* dst = &Ks[row * 65 + c4];
            dst[0] = v.x; dst[1] = v.y; dst[2] = v.z; dst[3] = v.w;
        }
        __syncthreads();
        float acc[8];
#pragma unroll
        for (int j = 0; j < 8; j++) acc[j] = 0.f;
        const float* qrow = &Qs[qi * 64];
#pragma unroll 16
        for (int d = 0; d < 64; d++) {
            float qd = qrow[d];
#pragma unroll
            for (int j = 0; j < 8; j++)
                acc[j] += qd * Ks[(l8 * 8 + j) * 65 + d];
        }
        float* srow = &Ss[qi * 520 + kt * 64 + l8 * 8];
#pragma unroll
        for (int j = 0; j < 8; j++) srow[j] = acc[j];
    }
    __syncthreads();

    // ---- softmax (8 lanes cooperate per query row) ----
    {
        float* row = &Ss[qi * 520];
        float m = -1e30f;
        for (int j = l8; j < 512; j += 8) m = fmaxf(m, row[j]);
#pragma unroll
        for (int o = 4; o >= 1; o >>= 1)
            m = fmaxf(m, __shfl_xor_sync(0xffffffffu, m, o, 8));
        float s = 0.f;
        for (int j = l8; j < 512; j += 8) {
            float e = __expf(row[j] - m);
            row[j] = e;
            s += e;
        }
#pragma unroll
        for (int o = 4; o >= 1; o >>= 1)
            s += __shfl_xor_sync(0xffffffffu, s, o, 8);
        float inv = 1.f / s;
        for (int j = l8; j < 512; j += 8) row[j] *= inv;
    }

    // ---- O = P V ----
    float oacc[8];
#pragma unroll
    for (int j = 0; j < 8; j++) oacc[j] = 0.f;
    for (int vt = 0; vt < 8; vt++) {
        __syncthreads();
        int f = tid;
#pragma unroll
        for (int it = 0; it < 4; it++, f += 256) {
            int row = f >> 4, c4 = (f & 15) * 4;
            float4 v = *(const float4*)(Vp + (size_t)(vt * 64 + row) * DD + c4);
            float* dst = &Ks[row * 65 + c4];
            dst[0] = v.x; dst[1] = v.y; dst[2] = v.z; dst[3] = v.w;
        }
        __syncthreads();
        const float* prow = &Ss[qi * 520 + vt * 64];
#pragma unroll 16
        for (int jj = 0; jj < 64; jj++) {
            float p = prow[jj];
#pragma unroll
            for (int j = 0; j < 8; j++)
                oacc[j] += p * Ks[jj * 65 + l8 * 8 + j];
        }
    }
    float* op = O + (size_t)(b * NNQ + q0 + qi) * DD + h * DKK + l8 * 8;
    *(float4*)op       = make_float4(oacc[0], oacc[1], oacc[2], oacc[3]);
    *(float4*)(op + 4) = make_float4(oacc[4], oacc[5], oacc[6], oacc[7]);
}

// ---------------- batch-norm: zero stats, column stats, normalize ---------
__global__ void zero_k(float* s, float* q)
{
    int i = threadIdx.x;
    s[i] = 0.f; q[i] = 0.f;
}

__global__ void stats_k(const float* __restrict__ y, float* __restrict__ gsum,
                        float* __restrict__ gsq)
{
    int c0 = threadIdx.x;                   // columns c0 and c0+256
    int r0 = blockIdx.x * (BNR / 64);       // 256 rows per block (64 blocks)
    float s0 = 0.f, q0 = 0.f, s1 = 0.f, q1 = 0.f;
    for (int r = r0; r < r0 + (BNR / 64); r++) {
        float v0 = y[(size_t)r * DD + c0];
        float v1 = y[(size_t)r * DD + c0 + 256];
        s0 += v0; q0 += v0 * v0;
        s1 += v1; q1 += v1 * v1;
    }
    atomicAdd(&gsum[c0], s0);        atomicAdd(&gsq[c0], q0);
    atomicAdd(&gsum[c0 + 256], s1);  atomicAdd(&gsq[c0 + 256], q1);
}

__global__ void apply_k(const float4* __restrict__ y, const float* __restrict__ gsum,
                        const float* __restrict__ gsq, const float* __restrict__ gamma,
                        const float* __restrict__ beta, float4* __restrict__ out)
{
    int idx = blockIdx.x * blockDim.x + threadIdx.x;
    if (idx >= BNR * DD / 4) return;
    int c0 = (idx & 127) * 4;
    const float inv = 1.f / (float)BNR;
    float4 v = y[idx];
    float r[4] = {v.x, v.y, v.z, v.w};
#pragma unroll
    for (int j = 0; j < 4; j++) {
        int c = c0 + j;
        float mu  = gsum[c] * inv;
        float var = gsq[c] * inv - mu * mu;
        r[j] = (r[j] - mu) * rsqrtf(var + EPSV) * gamma[c] + beta[c];
    }
    out[idx] = make_float4(r[0], r[1], r[2], r[3]);
}

// ---------------- final per-graph mean over nodes -------------------------
__global__ void mean_k(const float* __restrict__ h, float* __restrict__ out2)
{
    int b = blockIdx.x;
    int d = threadIdx.x;
    float s = 0.f;
    for (int n = 0; n < NNQ; n++)
        s += h[(size_t)(b * NNQ + n) * DD + d];
    out2[b * DD + d] = s * (1.f / (float)NNQ);
}

// ---------------- host orchestration --------------------------------------
extern "C" void kernel_launch(void* const* d_in, const int* in_sizes, int n_in,
                              void* d_out, int out_size)
{
    const float* x   = (const float*)d_in[0];
    const float* We  = (const float*)d_in[1];
    const float* be  = (const float*)d_in[2];
    const float* Wq  = (const float*)d_in[3];
    const float* Wk  = (const float*)d_in[4];
    const float* Wv  = (const float*)d_in[5];
    const float* Wo  = (const float*)d_in[6];
    const float* g1  = (const float*)d_in[7];
    const float* b1  = (const float*)d_in[8];
    const float* W1  = (const float*)d_in[9];
    const float* bb1 = (const float*)d_in[10];
    const float* W2  = (const float*)d_in[11];
    const float* bb2 = (const float*)d_in[12];
    const float* g2  = (const float*)d_in[13];
    const float* b2  = (const float*)d_in[14];
    float* out = (float*)d_out;

    float *h, *y, *att, *qkv, *ff, *wp, *gs, *gq;
    cudaGetSymbolAddress((void**)&h,   g_h);
    cudaGetSymbolAddress((void**)&y,   g_y);
    cudaGetSymbolAddress((void**)&att, g_att);
    cudaGetSymbolAddress((void**)&qkv, g_qkv);
    cudaGetSymbolAddress((void**)&ff,  g_ff);
    cudaGetSymbolAddress((void**)&wp,  g_wp);
    cudaGetSymbolAddress((void**)&gs,  g_sum);
    cudaGetSymbolAddress((void**)&gq,  g_sq);

    const int SMEM_ATT = (2048 + 4160 + 16640) * 4;  // 91392 B
    cudaFuncSetAttribute(attn_k, cudaFuncAttributeMaxDynamicSharedMemorySize, SMEM_ATT);

    pack_k<<<(LL * 3 * DD * DD) / 256, 256>>>(Wq, Wk, Wv, wp);
    embed_k<<<(BNR * DD) / 256, 256>>>(x, We, be, h);

    const size_t PER = (size_t)DD * DD;  // 262144
    for (int l = 0; l < LL; l++) {
        // QKV projections (packed weights are [K=512, N=512] row-major)
        gemm_k<false, false, false, false><<<dim3(4, 128), 256>>>(
            h, wp + (size_t)(l * 3 + 0) * PER, nullptr, nullptr, qkv,                BNR, DD, DD);
        gemm_k<false, false, false, false><<<dim3(4, 128), 256>>>(
            h, wp + (size_t)(l * 3 + 1) * PER, nullptr, nullptr, qkv + BNR * DD,     BNR, DD, DD);
        gemm_k<false, false, false, false><<<dim3(4, 128), 256>>>(
            h, wp + (size_t)(l * 3 + 2) * PER, nullptr, nullptr, qkv + 2 * BNR * DD, BNR, DD, DD);

        attn_k<<<dim3(16, BB * HH), 256, SMEM_ATT>>>(qkv, qkv + BNR * DD, qkv + 2 * BNR * DD, att);

        // output projection + residual (Wo already [H*DK, D] = [K,N] row-major)
        gemm_k<false, false, false, true><<<dim3(4, 128), 256>>>(
            att, Wo + l * PER, nullptr, h, y, BNR, DD, DD);

        zero_k<<<1, DD>>>(gs, gq);
        stats_k<<<64, 256>>>(y, gs, gq);
        apply_k<<<(BNR * DD / 4) / 256, 256>>>((const float4*)y, gs, gq,
                                               g1 + l * DD, b1 + l * DD, (float4*)h);

        // FFN
        gemm_k<true, true, true, false><<<dim3(16, 128), 256>>>(
            h, W1 + (size_t)l * FFF * DD, bb1 + (size_t)l * FFF, nullptr, ff, BNR, FFF, DD);
        gemm_k<true, true, false, true><<<dim3(4, 128), 256>>>(
            ff, W2 + (size_t)l * DD * FFF, bb2 + (size_t)l * DD, h, y, BNR, DD, FFF);

        zero_k<<<1, DD>>>(gs, gq);
        stats_k<<<64, 256>>>(y, gs, gq);
        float* dst = (l == LL - 1) ? out : h;
        apply_k<<<(BNR * DD / 4) / 256, 256>>>((const float4*)y, gs, gq,
                                               g2 + l * DD, b2 + l * DD, (float4*)dst);
    }

    mean_k<<<BB, DD>>>(out, out + (size_t)BNR * DD);
}

// round 17
// speedup vs baseline: 2.7811x; 2.7811x over previous
#include <cuda_runtime.h>
#include <cuda_bf16.h>
#include <cstdint>

#define BB   32
#define NNQ  512
#define DD   512
#define HH   8
#define LL   3
#define FFF  2048
#define BNR  (BB*NNQ)
#define EPSV 1e-5f

// ---------------- static scratch ----------------
__device__ float g_h  [BNR*DD];
__device__ float g_y  [BNR*DD];
__device__ float g_att[BNR*DD];
__device__ float g_qkv[(size_t)BNR*3*DD];
__device__ float g_ff [(size_t)BNR*FFF];
__device__ float g_sc [(size_t)BB*HH*NNQ*NNQ];   // 256 MB scores
__device__ float g_wp [(size_t)LL*3*DD*DD];      // packed QKV weights [l][1536][512]
__device__ float g_sum[DD];
__device__ float g_sq [DD];

// ---------------- helpers ----------------
__device__ __forceinline__ uint32_t smem_u32(const void* p) {
    uint32_t a;
    asm("{ .reg .u64 t; cvta.to.shared.u64 t, %1; cvt.u32.u64 %0, t; }" : "=r"(a) : "l"(p));
    return a;
}
__device__ __forceinline__ void ldm_x4(uint32_t* r, uint32_t addr) {
    asm volatile("ldmatrix.sync.aligned.m8n8.x4.shared.b16 {%0,%1,%2,%3}, [%4];"
        : "=r"(r[0]), "=r"(r[1]), "=r"(r[2]), "=r"(r[3]) : "r"(addr));
}
__device__ __forceinline__ void mma16816(float* c, const uint32_t* a, const uint32_t* b) {
    asm volatile("mma.sync.aligned.m16n8k16.row.col.f32.bf16.bf16.f32 "
        "{%0,%1,%2,%3}, {%4,%5,%6,%7}, {%8,%9}, {%0,%1,%2,%3};"
        : "+f"(c[0]), "+f"(c[1]), "+f"(c[2]), "+f"(c[3])
        : "r"(a[0]), "r"(a[1]), "r"(a[2]), "r"(a[3]), "r"(b[0]), "r"(b[1]));
}
// split fp32 -> bf16 hi/lo, store 4 contiguous halves to each
__device__ __forceinline__ void split4(__nv_bfloat16* hi, __nv_bfloat16* lo, float4 v) {
    float a[4] = {v.x, v.y, v.z, v.w};
    unsigned short hs[4], ls[4];
#pragma unroll
    for (int j = 0; j < 4; j++) {
        __nv_bfloat16 bh = __float2bfloat16(a[j]);
        hs[j] = __bfloat16_as_ushort(bh);
        ls[j] = __bfloat16_as_ushort(__float2bfloat16(a[j] - __bfloat162float(bh)));
    }
    *(uint2*)hi = make_uint2((uint32_t)hs[0] | ((uint32_t)hs[1] << 16),
                             (uint32_t)hs[2] | ((uint32_t)hs[3] << 16));
    *(uint2*)lo = make_uint2((uint32_t)ls[0] | ((uint32_t)ls[1] << 16),
                             (uint32_t)ls[2] | ((uint32_t)ls[3] << 16));
}

// ---------------- split-bf16 HMMA batched GEMM ----------------------------
// C[z; m, n] = sum_k A[z; m,k] * B[z; n,k]  (+bias[n]) (+res[m,n]) (relu)
// z = blockIdx.z decomposed z1=z>>3, z0=z&7 with strides (s1, s0).
// BT=true: B global layout is [K,N] with row stride ldb; else [N,K].
// Block tile 128 x TN, 8 warps (4m x 2n), K in chunks of 32, double-buffered.
template<int TN, bool BT, bool BIAS, bool RELU, bool RES>
__global__ void __launch_bounds__(256)
gemm_mma(const float* __restrict__ A, size_t lda, size_t sA1, size_t sA0,
         const float* __restrict__ B, size_t ldb, size_t sB1, size_t sB0,
         float* __restrict__ C, size_t ldc, size_t sC1, size_t sC0,
         const float* __restrict__ bias, const float* __restrict__ res,
         int K, float alpha)
{
    extern __shared__ __nv_bfloat16 sm[];
    constexpr int S   = 40;          // halves per row (padded, conflict-free ldmatrix)
    constexpr int ASZ = 128 * S;     // 5120 halves
    constexpr int BSZ = TN * S;
    constexpr int BUF = (ASZ + BSZ) * 2;   // halves per buffer (A hi/lo + B hi/lo)
    constexpr int NB  = TN / 32;     // float4 loads per thread for B per chunk
    constexpr int NQ  = TN / 16;     // n8 blocks per warp
    constexpr int N16 = TN / 32;     // n16 ldmatrix groups per warp

    int tid = threadIdx.x, lane = tid & 31, wid = tid >> 5;
    int wm = wid & 3, wn = wid >> 2;
    int m0 = blockIdx.y * 128, n0 = blockIdx.x * TN;
    int z = blockIdx.z, z1 = z >> 3, z0 = z & 7;
    const float* Ag = A + (size_t)z1 * sA1 + (size_t)z0 * sA0;
    const float* Bg = B + (size_t)z1 * sB1 + (size_t)z0 * sB0;
    float*       Cg = C + (size_t)z1 * sC1 + (size_t)z0 * sC0;

    uint32_t sbase = smem_u32(sm);

    float acc[2][NQ][4];
#pragma unroll
    for (int mi = 0; mi < 2; mi++)
#pragma unroll
        for (int q = 0; q < NQ; q++)
#pragma unroll
            for (int j = 0; j < 4; j++) acc[mi][q][j] = 0.f;

    float4 ra[4], rb[NB];

    auto loadA = [&](int kc) {
#pragma unroll
        for (int i = 0; i < 4; i++) {
            int g = tid + i * 256;
            ra[i] = *(const float4*)(Ag + (size_t)(m0 + (g >> 3)) * lda + (kc << 5) + ((g & 7) << 2));
        }
    };
    auto loadB = [&](int kc) {
        if (!BT) {
#pragma unroll
            for (int i = 0; i < NB; i++) {
                int g = tid + i * 256;
                rb[i] = *(const float4*)(Bg + (size_t)(n0 + (g >> 3)) * ldb + (kc << 5) + ((g & 7) << 2));
            }
        } else {
#pragma unroll
            for (int i = 0; i < NB; i++) {
                int g = tid + i * 256;
                int n4 = (g & (TN / 4 - 1)) << 2;
                int kk = g / (TN / 4);
                rb[i] = *(const float4*)(Bg + (size_t)((kc << 5) + kk) * ldb + n0 + n4);
            }
        }
    };
    auto storeS = [&](int b) {
        __nv_bfloat16* Ahi = sm + b * BUF;
        __nv_bfloat16* Alo = Ahi + ASZ;
        __nv_bfloat16* Bhi = Ahi + 2 * ASZ;
        __nv_bfloat16* Blo = Bhi + BSZ;
#pragma unroll
        for (int i = 0; i < 4; i++) {
            int g = tid + i * 256;
            int r = g >> 3, k4 = (g & 7) << 2;
            float4 v = ra[i];
            v.x *= alpha; v.y *= alpha; v.z *= alpha; v.w *= alpha;
            split4(Ahi + r * S + k4, Alo + r * S + k4, v);
        }
        if (!BT) {
#pragma unroll
            for (int i = 0; i < NB; i++) {
                int g = tid + i * 256;
                int r = g >> 3, k4 = (g & 7) << 2;
                split4(Bhi + r * S + k4, Blo + r * S + k4, rb[i]);
            }
        } else {
#pragma unroll
            for (int i = 0; i < NB; i++) {
                int g = tid + i * 256;
                int n4 = (g & (TN / 4 - 1)) << 2;
                int kk = g / (TN / 4);
                float vv[4] = {rb[i].x, rb[i].y, rb[i].z, rb[i].w};
#pragma unroll
                for (int j = 0; j < 4; j++) {
                    __nv_bfloat16 h = __float2bfloat16(vv[j]);
                    Bhi[(n4 + j) * S + kk] = h;
                    Blo[(n4 + j) * S + kk] = __float2bfloat16(vv[j] - __bfloat162float(h));
                }
            }
        }
    };
    auto compute = [&](int b) {
        uint32_t AhiB = sbase + (uint32_t)(b * BUF * 2);
        uint32_t AloB = AhiB + ASZ * 2;
        uint32_t BhiB = AhiB + 4 * ASZ;
        uint32_t BloB = BhiB + BSZ * 2;
        int arow = wm * 32 + (lane & 15);
        int acolb = (lane >> 4) << 3;
        int brow = wn * (TN / 2) + (lane & 7) + ((lane >> 4) << 3);
        int bcolb = ((lane >> 3) & 1) << 3;
#pragma unroll
        for (int ks = 0; ks < 2; ks++) {
            uint32_t ah[2][4], al[2][4];
#pragma unroll
            for (int mi = 0; mi < 2; mi++) {
                uint32_t off = (uint32_t)(((arow + mi * 16) * S + acolb + ks * 16) * 2);
                ldm_x4(ah[mi], AhiB + off);
                ldm_x4(al[mi], AloB + off);
            }
            uint32_t bh[N16][4], bl[N16][4];
#pragma unroll
            for (int j = 0; j < N16; j++) {
                uint32_t off = (uint32_t)(((brow + j * 16) * S + bcolb + ks * 16) * 2);
                ldm_x4(bh[j], BhiB + off);
                ldm_x4(bl[j], BloB + off);
            }
#pragma unroll
            for (int mi = 0; mi < 2; mi++)
#pragma unroll
                for (int q = 0; q < NQ; q++)
                    mma16816(acc[mi][q], ah[mi], &bh[q >> 1][(q & 1) * 2]);
#pragma unroll
            for (int mi = 0; mi < 2; mi++)
#pragma unroll
                for (int q = 0; q < NQ; q++)
                    mma16816(acc[mi][q], ah[mi], &bl[q >> 1][(q & 1) * 2]);
#pragma unroll
            for (int mi = 0; mi < 2; mi++)
#pragma unroll
                for (int q = 0; q < NQ; q++)
                    mma16816(acc[mi][q], al[mi], &bh[q >> 1][(q & 1) * 2]);
        }
    };

    int nk = K >> 5;
    loadA(0); loadB(0);
    storeS(0);
    for (int c = 0; c < nk; c++) {
        __syncthreads();
        if (c + 1 < nk) { loadA(c + 1); loadB(c + 1); }
        compute(c & 1);
        if (c + 1 < nk) storeS((c + 1) & 1);
    }

    // ---- epilogue: fragment-layout fused stores ----
    int crow = m0 + wm * 32 + (lane >> 2);
    int ccol0 = n0 + wn * (TN / 2) + (lane & 3) * 2;
#pragma unroll
    for (int mi = 0; mi < 2; mi++) {
#pragma unroll
        for (int q = 0; q < NQ; q++) {
            int c = ccol0 + q * 8;
            int r0 = crow + mi * 16, r1 = r0 + 8;
            float2 v0 = make_float2(acc[mi][q][0], acc[mi][q][1]);
            float2 v1 = make_float2(acc[mi][q][2], acc[mi][q][3]);
            if (BIAS) {
                float2 b = *(const float2*)(bias + c);
                v0.x += b.x; v0.y += b.y; v1.x += b.x; v1.y += b.y;
            }
            if (RES) {
                float2 q0 = *(const float2*)(res + (size_t)r0 * ldc + c);
                float2 q1 = *(const float2*)(res + (size_t)r1 * ldc + c);
                v0.x += q0.x; v0.y += q0.y; v1.x += q1.x; v1.y += q1.y;
            }
            if (RELU) {
                v0.x = fmaxf(v0.x, 0.f); v0.y = fmaxf(v0.y, 0.f);
                v1.x = fmaxf(v1.x, 0.f); v1.y = fmaxf(v1.y, 0.f);
            }
            *(float2*)(Cg + (size_t)r0 * ldc + c) = v0;
            *(float2*)(Cg + (size_t)r1 * ldc + c) = v1;
        }
    }
}

// ---------------- pack Wq/Wk/Wv -> wp[l][n=t*512+h*64+dk][k=d] ------------
__global__ void pack_k(const float* __restrict__ Wq, const float* __restrict__ Wk,
                       const float* __restrict__ Wv, float* __restrict__ wp)
{
    size_t idx = (size_t)blockIdx.x * 256 + threadIdx.x;
    if (idx >= (size_t)LL * 1536 * 512) return;
    int l = (int)(idx / (1536 * 512));
    int rem = (int)(idx % (1536 * 512));
    int n = rem >> 9, k = rem & 511;
    int t = n >> 9, hdk = n & 511;
    const float* s = (t == 0) ? Wq : (t == 1) ? Wk : Wv;
    wp[idx] = s[((size_t)(l * HH + (hdk >> 6)) * 512 + k) * 64 + (hdk & 63)];
}

// ---------------- embed ----------------
__global__ void embed_k(const float* __restrict__ x, const float* __restrict__ We,
                        const float* __restrict__ be, float* __restrict__ h)
{
    int idx = blockIdx.x * blockDim.x + threadIdx.x;
    if (idx >= BNR * DD) return;
    int bn = idx >> 9, d = idx & 511;
    h[idx] = x[bn * 2] * We[d * 2] + x[bn * 2 + 1] * We[d * 2 + 1] + be[d];
}

// ---------------- softmax: one warp per 512-wide row ----------------
__global__ void __launch_bounds__(256) softmax_k(float* __restrict__ sc)
{
    size_t row = (size_t)blockIdx.x * 8 + (threadIdx.x >> 5);
    int lane = threadIdx.x & 31;
    float* p = sc + row * 512 + lane * 4;
    float4 v[4];
#pragma unroll
    for (int i = 0; i < 4; i++) v[i] = *(float4*)(p + i * 128);
    float m = -1e30f;
#pragma unroll
    for (int i = 0; i < 4; i++)
        m = fmaxf(m, fmaxf(fmaxf(v[i].x, v[i].y), fmaxf(v[i].z, v[i].w)));
#pragma unroll
    for (int o = 16; o >= 1; o >>= 1) m = fmaxf(m, __shfl_xor_sync(0xffffffffu, m, o));
    float s = 0.f;
#pragma unroll
    for (int i = 0; i < 4; i++) {
        v[i].x = __expf(v[i].x - m); v[i].y = __expf(v[i].y - m);
        v[i].z = __expf(v[i].z - m); v[i].w = __expf(v[i].w - m);
        s += v[i].x + v[i].y + v[i].z + v[i].w;
    }
#pragma unroll
    for (int o = 16; o >= 1; o >>= 1) s += __shfl_xor_sync(0xffffffffu, s, o);
    float inv = 1.f / s;
#pragma unroll
    for (int i = 0; i < 4; i++) {
        v[i].x *= inv; v[i].y *= inv; v[i].z *= inv; v[i].w *= inv;
        *(float4*)(p + i * 128) = v[i];
    }
}

// ---------------- batch-norm ----------------
__global__ void zero_k(float* s, float* q) { int i = threadIdx.x; s[i] = 0.f; q[i] = 0.f; }

__global__ void stats_k(const float* __restrict__ y, float* __restrict__ gsum,
                        float* __restrict__ gsq)
{
    int c0 = threadIdx.x;
    int r0 = blockIdx.x * 64;
    float s0 = 0.f, q0 = 0.f, s1 = 0.f, q1 = 0.f;
    for (int r = r0; r < r0 + 64; r++) {
        float v0 = y[(size_t)r * DD + c0];
        float v1 = y[(size_t)r * DD + c0 + 256];
        s0 += v0; q0 += v0 * v0;
        s1 += v1; q1 += v1 * v1;
    }
    atomicAdd(&gsum[c0], s0);        atomicAdd(&gsq[c0], q0);
    atomicAdd(&gsum[c0 + 256], s1);  atomicAdd(&gsq[c0 + 256], q1);
}

__global__ void apply_k(const float4* __restrict__ y, const float* __restrict__ gsum,
                        const float* __restrict__ gsq, const float* __restrict__ gamma,
                        const float* __restrict__ beta, float4* __restrict__ out)
{
    int idx = blockIdx.x * blockDim.x + threadIdx.x;
    if (idx >= BNR * DD / 4) return;
    int c0 = (idx & 127) * 4;
    const float inv = 1.f / (float)BNR;
    float4 v = y[idx];
    float r[4] = {v.x, v.y, v.z, v.w};
#pragma unroll
    for (int j = 0; j < 4; j++) {
        int c = c0 + j;
        float mu  = gsum[c] * inv;
        float var = gsq[c] * inv - mu * mu;
        r[j] = (r[j] - mu) * rsqrtf(var + EPSV) * gamma[c] + beta[c];
    }
    out[idx] = make_float4(r[0], r[1], r[2], r[3]);
}

__global__ void mean_k(const float* __restrict__ h, float* __restrict__ out2)
{
    int b = blockIdx.x;
    int d = threadIdx.x;
    float s = 0.f;
    for (int n = 0; n < NNQ; n++)
        s += h[(size_t)(b * NNQ + n) * DD + d];
    out2[b * DD + d] = s * (1.f / (float)NNQ);
}

// ---------------- host orchestration ----------------
extern "C" void kernel_launch(void* const* d_in, const int* in_sizes, int n_in,
                              void* d_out, int out_size)
{
    const float* x   = (const float*)d_in[0];
    const float* We  = (const float*)d_in[1];
    const float* be  = (const float*)d_in[2];
    const float* Wq  = (const float*)d_in[3];
    const float* Wk  = (const float*)d_in[4];
    const float* Wv  = (const float*)d_in[5];
    const float* Wo  = (const float*)d_in[6];
    const float* g1  = (const float*)d_in[7];
    const float* b1  = (const float*)d_in[8];
    const float* W1  = (const float*)d_in[9];
    const float* bb1 = (const float*)d_in[10];
    const float* W2  = (const float*)d_in[11];
    const float* bb2 = (const float*)d_in[12];
    const float* g2  = (const float*)d_in[13];
    const float* b2  = (const float*)d_in[14];
    float* out = (float*)d_out;

    float *h, *y, *att, *qkv, *ff, *sc, *wp, *gs, *gq;
    cudaGetSymbolAddress((void**)&h,   g_h);
    cudaGetSymbolAddress((void**)&y,   g_y);
    cudaGetSymbolAddress((void**)&att, g_att);
    cudaGetSymbolAddress((void**)&qkv, g_qkv);
    cudaGetSymbolAddress((void**)&ff,  g_ff);
    cudaGetSymbolAddress((void**)&sc,  g_sc);
    cudaGetSymbolAddress((void**)&wp,  g_wp);
    cudaGetSymbolAddress((void**)&gs,  g_sum);
    cudaGetSymbolAddress((void**)&gq,  g_sq);

    const int SM128 = ((128 * 40 + 128 * 40) * 2 * 2) * 2;  // 81920 B
    const int SM64  = ((128 * 40 + 64 * 40) * 2 * 2) * 2;   // 61440 B
    cudaFuncSetAttribute(gemm_mma<128,false,false,false,false>, cudaFuncAttributeMaxDynamicSharedMemorySize, SM128);
    cudaFuncSetAttribute(gemm_mma<64, true, false,false,false>, cudaFuncAttributeMaxDynamicSharedMemorySize, SM64);
    cudaFuncSetAttribute(gemm_mma<128,true, false,false,true >, cudaFuncAttributeMaxDynamicSharedMemorySize, SM128);
    cudaFuncSetAttribute(gemm_mma<128,false,true, true, false>, cudaFuncAttributeMaxDynamicSharedMemorySize, SM128);
    cudaFuncSetAttribute(gemm_mma<128,false,true, false,true >, cudaFuncAttributeMaxDynamicSharedMemorySize, SM128);

    pack_k<<<(LL * 1536 * 512) / 256, 256>>>(Wq, Wk, Wv, wp);
    embed_k<<<(BNR * DD) / 256, 256>>>(x, We, be, h);

    for (int l = 0; l < LL; l++) {
        const float* wpl = wp + (size_t)l * 1536 * 512;
        // merged QKV: qkv[16384 x 1536] = h @ wp^T
        gemm_mma<128,false,false,false,false><<<dim3(12,128,1), 256, SM128>>>(
            h, 512, 0, 0,  wpl, 512, 0, 0,  qkv, 1536, 0, 0,
            nullptr, nullptr, 512, 1.f);
        // S = (Q*0.125) K^T, 256 batches (z1=b stride 786432, z0=h stride 64)
        gemm_mma<128,false,false,false,false><<<dim3(4,4,256), 256, SM128>>>(
            qkv,       1536, 786432, 64,
            qkv + 512, 1536, 786432, 64,
            sc,         512, 2097152, 262144,
            nullptr, nullptr, 64, 0.125f);
        softmax_k<<<(BB*HH*NNQ)/8, 256>>>(sc);
        // O = P V  (B = V in [K=token, N=dk] layout -> BT)
        gemm_mma<64,true,false,false,false><<<dim3(1,4,256), 256, SM64>>>(
            sc,          512, 2097152, 262144,
            qkv + 1024, 1536, 786432, 64,
            att,         512, 262144, 64,
            nullptr, nullptr, 512, 1.f);
        // y = att @ Wo + h   (Wo is [K=512, N=512] -> BT)
        gemm_mma<128,true,false,false,true><<<dim3(4,128,1), 256, SM128>>>(
            att, 512, 0, 0,  Wo + (size_t)l * 262144, 512, 0, 0,
            y, 512, 0, 0,  nullptr, h, 512, 1.f);

        zero_k<<<1, DD>>>(gs, gq);
        stats_k<<<256, 256>>>(y, gs, gq);
        apply_k<<<(BNR * DD / 4) / 256, 256>>>((const float4*)y, gs, gq,
                                               g1 + l * DD, b1 + l * DD, (float4*)h);
        // ff = relu(h @ W1^T + bb1)
        gemm_mma<128,false,true,true,false><<<dim3(16,128,1), 256, SM128>>>(
            h, 512, 0, 0,  W1 + (size_t)l * FFF * DD, 512, 0, 0,
            ff, 2048, 0, 0,  bb1 + (size_t)l * FFF, nullptr, 512, 1.f);
        // y = ff @ W2^T + bb2 + h
        gemm_mma<128,false,true,false,true><<<dim3(4,128,1), 256, SM128>>>(
            ff, 2048, 0, 0,  W2 + (size_t)l * DD * FFF, 2048, 0, 0,
            y, 512, 0, 0,  bb2 + (size_t)l * DD, h, 2048, 1.f);

        zero_k<<<1, DD>>>(gs, gq);
        stats_k<<<256, 256>>>(y, gs, gq);
        float* dst = (l == LL - 1) ? out : h;
        apply_k<<<(BNR * DD / 4) / 256, 256>>>((const float4*)y, gs, gq,
                                               g2 + l * DD, b2 + l * DD, (float4*)dst);
    }

    mean_k<<<BB, DD>>>(out, out + (size_t)BNR * DD);
}